// round 11
// baseline (speedup 1.0000x reference)
#include <cuda_runtime.h>
#include <cstdint>

#define BB 256
#define CC 2048
#define HWN 49
#define KK 16
typedef unsigned long long ull;

// Static device scratch
__device__ __align__(16) float g_part[BB * 16 * 784]; // [b][p<16][k*49+hw]
__device__ __align__(16) float g_fc16[BB * 784];      // [b][hw*16+k], BN'd, /49
__device__ __align__(16) float g_wT[CC * KK];         // [c][16]
__device__ float g_binv[KK], g_boff[KK];

__device__ __forceinline__ ull ffma2(ull a, ull b, ull c) {
    ull d;
    asm("fma.rn.f32x2 %0, %1, %2, %3;" : "=l"(d) : "l"(a), "l"(b), "l"(c));
    return d;
}
__device__ __forceinline__ ull pack2(float x, float y) {
    ull r;
    asm("mov.b64 %0, {%1, %2};" : "=l"(r) : "f"(x), "f"(y));
    return r;
}
__device__ __forceinline__ void unpack2(ull v, float& x, float& y) {
    asm("mov.b64 {%0, %1}, %2;" : "=f"(x), "=f"(y) : "l"(v));
}
__device__ __forceinline__ uint32_t smem_u32(const void* p) {
    uint32_t a;
    asm("{ .reg .u64 t; cvta.to.shared.u64 t, %1; cvt.u32.u64 %0, t; }"
        : "=r"(a) : "l"(p));
    return a;
}
__device__ __forceinline__ void mbar_init1(uint32_t mbar_a) {
    asm volatile("mbarrier.init.shared.b64 [%0], %1;" :: "r"(mbar_a), "r"(1));
}
__device__ __forceinline__ void mbar_wait0(uint32_t mbar_a) {
    uint32_t done;
    asm volatile(
        "{\n\t.reg .pred p;\n\t"
        "mbarrier.try_wait.parity.acquire.cta.shared::cta.b64 p, [%1], 0;\n\t"
        "selp.b32 %0, 1, 0, p;\n\t}"
        : "=r"(done) : "r"(mbar_a) : "memory");
    if (!done) {
        asm volatile(
            "{\n\t.reg .pred P1;\n\t"
            "W%=:\n\t"
            "mbarrier.try_wait.parity.acquire.cta.shared::cta.b64 P1, [%0], 0, 0x989680;\n\t"
            "@P1 bra.uni D%=;\n\t"
            "bra.uni W%=;\n\t"
            "D%=:\n\t}"
            :: "r"(mbar_a) : "memory");
    }
}
__device__ __forceinline__ void tma_bulk_1d(uint32_t dst_smem, const void* src,
                                            uint32_t bytes, uint32_t mbar_a) {
    asm volatile(
        "cp.async.bulk.shared::cta.global.mbarrier::complete_tx::bytes [%0], [%1], %2, [%3];"
        :: "r"(dst_smem), "l"(src), "r"(bytes), "r"(mbar_a) : "memory");
}

// ============================================================================
// K0: transpose weights -> g_wT[c][16]; BN constants (1/49 folded)
// ============================================================================
__global__ void k0_prep(const float* __restrict__ w16,
                        const float* __restrict__ bng, const float* __restrict__ bnb,
                        const float* __restrict__ bnm, const float* __restrict__ bnv) {
    int idx = blockIdx.x * 256 + threadIdx.x;
    if (idx < CC * KK) {
        int c = idx >> 4, k = idx & 15;
        g_wT[idx] = w16[k * CC + c];
    }
    if (blockIdx.x == 0 && threadIdx.x < KK) {
        int k = threadIdx.x;
        float iv = bng[k] * rsqrtf(bnv[k] + 1e-5f);
        g_binv[k] = iv * (1.0f / 49.0f);
        g_boff[k] = (bnb[k] - bnm[k] * iv) * (1.0f / 49.0f);
    }
}

// ============================================================================
// K1: partial conv, TMA-staged. Block = (q-slice of 512 c, b), 128 threads.
// fm tile (100KB) via cp.async.bulk. Warp w owns 128 c. Per c: 2 conflict-free
// LDS.32 (lanes->hw) + 4 uniform L1-hit LDG.128 weight quads (depth-1
// prefetch) + 16 FFMA2. Each warp stores its own 784-float partial to g_part
// (no cross-warp reduce, no post-compute sync). 2 blocks/SM.
// ============================================================================
#define K1_TILE_BYTES (512 * HWN * 4)   // 100352
#define K1_SMEM (K1_TILE_BYTES + 16)

__global__ __launch_bounds__(128, 2) void k1_conv(const float* __restrict__ fm) {
    extern __shared__ __align__(16) float smem1[];
    float* fms = smem1;                               // [512][49]
    ull* mbar = (ull*)(smem1 + 512 * HWN);

    const int b = blockIdx.y, q = blockIdx.x;
    const int tid = threadIdx.x;
    const int lane = tid & 31, wid = tid >> 5;
    const bool hi = (lane < 17);
    const int cbase = q * 512;

    uint32_t mbar_a = smem_u32(mbar);
    if (tid == 0) mbar_init1(mbar_a);
    __syncthreads();
    if (tid == 0) {
        asm volatile("mbarrier.arrive.expect_tx.shared.b64 _, [%0], %1;"
                     :: "r"(mbar_a), "r"((uint32_t)K1_TILE_BYTES));
        tma_bulk_1d(smem_u32(fms),
                    fm + (size_t)b * (CC * HWN) + (size_t)cbase * HWN,
                    K1_TILE_BYTES, mbar_a);
    }
    mbar_wait0(mbar_a);

    const float* fmw = fms + wid * 128 * HWN;
    const float* wq = g_wT + (cbase + wid * 128) * KK;

    ull acc0[8], acc1[8];
#pragma unroll
    for (int i = 0; i < 8; i++) { acc0[i] = 0ull; acc1[i] = 0ull; }

    // depth-1 prefetch of weight quads (uniform LDG.128, dedup'd on return bus)
    const ulonglong2* wp0 = (const ulonglong2*)wq;
    ulonglong2 wA = wp0[0], wB = wp0[1], wC = wp0[2], wD = wp0[3];

#pragma unroll 4
    for (int j = 0; j < 128; j++) {
        ulonglong2 nA, nB, nC, nD;
        if (j < 127) {
            const ulonglong2* wp = (const ulonglong2*)(wq + (j + 1) * KK);
            nA = wp[0]; nB = wp[1]; nC = wp[2]; nD = wp[3];
        }
        float v0 = fmw[j * HWN + lane];
        float v1 = hi ? fmw[j * HWN + lane + 32] : 0.0f;
        ull vv0 = pack2(v0, v0), vv1 = pack2(v1, v1);

        acc0[0] = ffma2(wA.x, vv0, acc0[0]);  acc1[0] = ffma2(wA.x, vv1, acc1[0]);
        acc0[1] = ffma2(wA.y, vv0, acc0[1]);  acc1[1] = ffma2(wA.y, vv1, acc1[1]);
        acc0[2] = ffma2(wB.x, vv0, acc0[2]);  acc1[2] = ffma2(wB.x, vv1, acc1[2]);
        acc0[3] = ffma2(wB.y, vv0, acc0[3]);  acc1[3] = ffma2(wB.y, vv1, acc1[3]);
        acc0[4] = ffma2(wC.x, vv0, acc0[4]);  acc1[4] = ffma2(wC.x, vv1, acc1[4]);
        acc0[5] = ffma2(wC.y, vv0, acc0[5]);  acc1[5] = ffma2(wC.y, vv1, acc1[5]);
        acc0[6] = ffma2(wD.x, vv0, acc0[6]);  acc1[6] = ffma2(wD.x, vv1, acc1[6]);
        acc0[7] = ffma2(wD.y, vv0, acc0[7]);  acc1[7] = ffma2(wD.y, vv1, acc1[7]);

        wA = nA; wB = nB; wC = nC; wD = nD;
    }

    // each warp writes its own partial: g_part[b][q*4+wid][k*49+hw]
    float* dst = g_part + ((size_t)b * 16 + q * 4 + wid) * 784;
#pragma unroll
    for (int kp = 0; kp < 8; kp++) {
        float a, c0;
        unpack2(acc0[kp], a, c0);
        dst[(2 * kp) * 49 + lane] = a;
        dst[(2 * kp + 1) * 49 + lane] = c0;
        if (hi) {
            float x, y;
            unpack2(acc1[kp], x, y);
            dst[(2 * kp) * 49 + lane + 32] = x;
            dst[(2 * kp + 1) * 49 + lane + 32] = y;
        }
    }
}

// ============================================================================
// K1b: reduce 16 partials, apply BN, relayout [k*49+hw] -> [hw*16+k]
// ============================================================================
__global__ __launch_bounds__(784) void k1b_reduce() {
    const int b = blockIdx.x;
    const int o = threadIdx.x;
    const float* src = g_part + (size_t)b * 16 * 784;
    float s = 0.0f;
#pragma unroll
    for (int p = 0; p < 16; p++) s += src[p * 784 + o];
    int k = o / 49;
    int hw = o - k * 49;
    g_fc16[b * 784 + hw * 16 + k] = s * g_binv[k] + g_boff[k];
}

// ============================================================================
// K2: bilinear (unchanged winning R10 design). Block = (c-tile 512, b
// REVERSED), 128 thr, 4 c/thread. TMA-staged fm + fc16; fc quads via uniform
// LDS.128 depth-1 prefetch, amortized over 4 c = 32 FFMA2.
// ============================================================================
#define K2_TILE_BYTES (512 * HWN * 4)      // 100352
#define K2_FC_BYTES   (784 * 4)            // 3136
#define K2_SMEM (K2_TILE_BYTES + K2_FC_BYTES + 16)

__global__ __launch_bounds__(128, 2) void k2_bilinear(const float* __restrict__ fm,
                                                      float* __restrict__ out) {
    extern __shared__ __align__(16) float smem[];
    float* fms = smem;                       // [512][49]
    float* fcs = smem + 512 * HWN;           // [hw][16]
    ull* mbar = (ull*)(smem + 512 * HWN + 784);

    const int tid = threadIdx.x;
    const int b = (BB - 1) - blockIdx.y;     // reverse-b: ride K1's L2 tail
    const int cbase = blockIdx.x * 512;

    uint32_t mbar_a = smem_u32(mbar);
    if (tid == 0) mbar_init1(mbar_a);
    __syncthreads();
    if (tid == 0) {
        asm volatile("mbarrier.arrive.expect_tx.shared.b64 _, [%0], %1;"
                     :: "r"(mbar_a), "r"((uint32_t)(K2_TILE_BYTES + K2_FC_BYTES)));
        tma_bulk_1d(smem_u32(fms),
                    fm + (size_t)b * (CC * HWN) + (size_t)cbase * HWN,
                    K2_TILE_BYTES, mbar_a);
        tma_bulk_1d(smem_u32(fcs), g_fc16 + (size_t)b * 784, K2_FC_BYTES, mbar_a);
    }
    mbar_wait0(mbar_a);

    const float* r0 = &fms[tid * HWN];
    const float* r1 = &fms[(tid + 128) * HWN];
    const float* r2 = &fms[(tid + 256) * HWN];
    const float* r3 = &fms[(tid + 384) * HWN];
    const ulonglong2* fq = (const ulonglong2*)fcs;

    ull acc[4][8];
#pragma unroll
    for (int i = 0; i < 4; i++)
#pragma unroll
        for (int j = 0; j < 8; j++) acc[i][j] = 0ull;

    ulonglong2 q0 = fq[0], q1 = fq[1], q2 = fq[2], q3 = fq[3];

#pragma unroll 7
    for (int hw = 0; hw < HWN; hw++) {
        ulonglong2 n0, n1, n2, n3;
        if (hw < HWN - 1) {
            n0 = fq[(hw + 1) * 4 + 0];
            n1 = fq[(hw + 1) * 4 + 1];
            n2 = fq[(hw + 1) * 4 + 2];
            n3 = fq[(hw + 1) * 4 + 3];
        }
        float va = r0[hw], vb = r1[hw], vc = r2[hw], vd = r3[hw];
        ull vva = pack2(va, va), vvb = pack2(vb, vb);
        ull vvc = pack2(vc, vc), vvd = pack2(vd, vd);

        acc[0][0] = ffma2(q0.x, vva, acc[0][0]);  acc[1][0] = ffma2(q0.x, vvb, acc[1][0]);
        acc[2][0] = ffma2(q0.x, vvc, acc[2][0]);  acc[3][0] = ffma2(q0.x, vvd, acc[3][0]);
        acc[0][1] = ffma2(q0.y, vva, acc[0][1]);  acc[1][1] = ffma2(q0.y, vvb, acc[1][1]);
        acc[2][1] = ffma2(q0.y, vvc, acc[2][1]);  acc[3][1] = ffma2(q0.y, vvd, acc[3][1]);
        acc[0][2] = ffma2(q1.x, vva, acc[0][2]);  acc[1][2] = ffma2(q1.x, vvb, acc[1][2]);
        acc[2][2] = ffma2(q1.x, vvc, acc[2][2]);  acc[3][2] = ffma2(q1.x, vvd, acc[3][2]);
        acc[0][3] = ffma2(q1.y, vva, acc[0][3]);  acc[1][3] = ffma2(q1.y, vvb, acc[1][3]);
        acc[2][3] = ffma2(q1.y, vvc, acc[2][3]);  acc[3][3] = ffma2(q1.y, vvd, acc[3][3]);
        acc[0][4] = ffma2(q2.x, vva, acc[0][4]);  acc[1][4] = ffma2(q2.x, vvb, acc[1][4]);
        acc[2][4] = ffma2(q2.x, vvc, acc[2][4]);  acc[3][4] = ffma2(q2.x, vvd, acc[3][4]);
        acc[0][5] = ffma2(q2.y, vva, acc[0][5]);  acc[1][5] = ffma2(q2.y, vvb, acc[1][5]);
        acc[2][5] = ffma2(q2.y, vvc, acc[2][5]);  acc[3][5] = ffma2(q2.y, vvd, acc[3][5]);
        acc[0][6] = ffma2(q3.x, vva, acc[0][6]);  acc[1][6] = ffma2(q3.x, vvb, acc[1][6]);
        acc[2][6] = ffma2(q3.x, vvc, acc[2][6]);  acc[3][6] = ffma2(q3.x, vvd, acc[3][6]);
        acc[0][7] = ffma2(q3.y, vva, acc[0][7]);  acc[1][7] = ffma2(q3.y, vvb, acc[1][7]);
        acc[2][7] = ffma2(q3.y, vvc, acc[2][7]);  acc[3][7] = ffma2(q3.y, vvd, acc[3][7]);

        q0 = n0; q1 = n1; q2 = n2; q3 = n3;
    }

#pragma unroll
    for (int i = 0; i < 4; i++) {
        float* ob = out + (size_t)b * 32768 + cbase + i * 128 + tid;
#pragma unroll
        for (int kp = 0; kp < 8; kp++) {
            float x, y;
            unpack2(acc[i][kp], x, y);
            ob[(2 * kp) * 2048] = x;
            ob[(2 * kp + 1) * 2048] = y;
        }
    }
}

extern "C" void kernel_launch(void* const* d_in, const int* in_sizes, int n_in,
                              void* d_out, int out_size) {
    const float* fm  = (const float*)d_in[0];  // [256,2048,7,7]
    const float* w16 = (const float*)d_in[1];  // [16,2048]
    const float* bng = (const float*)d_in[2];
    const float* bnb = (const float*)d_in[3];
    const float* bnm = (const float*)d_in[4];
    const float* bnv = (const float*)d_in[5];
    float* out = (float*)d_out;

    cudaFuncSetAttribute(k1_conv, cudaFuncAttributeMaxDynamicSharedMemorySize,
                         K1_SMEM);
    cudaFuncSetAttribute(k2_bilinear, cudaFuncAttributeMaxDynamicSharedMemorySize,
                         K2_SMEM);

    k0_prep<<<(CC * KK + 255) / 256, 256>>>(w16, bng, bnb, bnm, bnv);
    dim3 g1(4, BB);       // 1024 blocks: (q-slice of 512c, b)
    k1_conv<<<g1, 128, K1_SMEM>>>(fm);
    k1b_reduce<<<BB, 784>>>();
    dim3 g2(4, BB);       // 1024 blocks: (c-tile of 512, b)
    k2_bilinear<<<g2, 128, K2_SMEM>>>(fm, out);
}

// round 12
// speedup vs baseline: 1.3910x; 1.3910x over previous
#include <cuda_runtime.h>
#include <cstdint>

#define BB 256
#define CC 2048
#define HWN 49
#define KK 16
typedef unsigned long long ull;

// Static device scratch
__device__ __align__(16) float g_part[BB * 32 * 784]; // [b][slice<32][k*49+hw]
__device__ __align__(16) float g_fc16[BB * 784];      // [b][hw*16+k], BN'd, /49
__device__ __align__(16) float g_wT[CC * KK];         // [c][16]
__device__ float g_binv[KK], g_boff[KK];

__device__ __forceinline__ ull ffma2(ull a, ull b, ull c) {
    ull d;
    asm("fma.rn.f32x2 %0, %1, %2, %3;" : "=l"(d) : "l"(a), "l"(b), "l"(c));
    return d;
}
__device__ __forceinline__ ull pack2(float x, float y) {
    ull r;
    asm("mov.b64 %0, {%1, %2};" : "=l"(r) : "f"(x), "f"(y));
    return r;
}
__device__ __forceinline__ void unpack2(ull v, float& x, float& y) {
    asm("mov.b64 {%0, %1}, %2;" : "=f"(x), "=f"(y) : "l"(v));
}
__device__ __forceinline__ uint32_t smem_u32(const void* p) {
    uint32_t a;
    asm("{ .reg .u64 t; cvta.to.shared.u64 t, %1; cvt.u32.u64 %0, t; }"
        : "=r"(a) : "l"(p));
    return a;
}
__device__ __forceinline__ void mbar_init1(uint32_t mbar_a) {
    asm volatile("mbarrier.init.shared.b64 [%0], %1;" :: "r"(mbar_a), "r"(1));
}
__device__ __forceinline__ void mbar_expect(uint32_t mbar_a, uint32_t bytes) {
    asm volatile("mbarrier.arrive.expect_tx.shared.b64 _, [%0], %1;"
                 :: "r"(mbar_a), "r"(bytes));
}
__device__ __forceinline__ void mbar_wait0(uint32_t mbar_a) {
    uint32_t done;
    asm volatile(
        "{\n\t.reg .pred p;\n\t"
        "mbarrier.try_wait.parity.acquire.cta.shared::cta.b64 p, [%1], 0;\n\t"
        "selp.b32 %0, 1, 0, p;\n\t}"
        : "=r"(done) : "r"(mbar_a) : "memory");
    if (!done) {
        asm volatile(
            "{\n\t.reg .pred P1;\n\t"
            "W%=:\n\t"
            "mbarrier.try_wait.parity.acquire.cta.shared::cta.b64 P1, [%0], 0, 0x989680;\n\t"
            "@P1 bra.uni D%=;\n\t"
            "bra.uni W%=;\n\t"
            "D%=:\n\t}"
            :: "r"(mbar_a) : "memory");
    }
}
__device__ __forceinline__ void tma_bulk_1d(uint32_t dst_smem, const void* src,
                                            uint32_t bytes, uint32_t mbar_a) {
    asm volatile(
        "cp.async.bulk.shared::cta.global.mbarrier::complete_tx::bytes [%0], [%1], %2, [%3];"
        :: "r"(dst_smem), "l"(src), "r"(bytes), "r"(mbar_a) : "memory");
}

// ============================================================================
// K0: transpose weights -> g_wT[c][16]; BN constants (1/49 folded)
// ============================================================================
__global__ void k0_prep(const float* __restrict__ w16,
                        const float* __restrict__ bng, const float* __restrict__ bnb,
                        const float* __restrict__ bnm, const float* __restrict__ bnv) {
    int idx = blockIdx.x * 256 + threadIdx.x;
    if (idx < CC * KK) {
        int c = idx >> 4, k = idx & 15;
        g_wT[idx] = w16[k * CC + c];
    }
    if (blockIdx.x == 0 && threadIdx.x < KK) {
        int k = threadIdx.x;
        float iv = bng[k] * rsqrtf(bnv[k] + 1e-5f);
        g_binv[k] = iv * (1.0f / 49.0f);
        g_boff[k] = (bnb[k] - bnm[k] * iv) * (1.0f / 49.0f);
    }
}

// ============================================================================
// K1: partial conv, G=4 batch-grouped + k-split, staggered TMA.
// Block = (q-slice of 128 c, b-quad), 128 threads. Warp = (c-sub s, k-half h):
// owns 64 c, 8 k, all 4 b. Per warp-c: 8 LDS.32 fm (8cyc) + 32B/lane weights
// (8cyc) vs 32 FFMA2 (16cyc) -> LSU/FMA balanced. Warp waits only its own
// c-chunk mbarrier (stagger). fm tile 100KB -> 2 blocks/SM.
// ============================================================================
#define K1_BCH (128 * HWN * 4)      // 25088 B: one b's 128-c slab
#define K1_CCH (64 * HWN * 4)       // 12544 B: one (b, c-half) chunk
#define K1_FM_FLOATS (4 * 128 * HWN)
#define K1_SMEM (K1_FM_FLOATS * 4 + 128 * KK * 4 + 64)

__global__ __launch_bounds__(128) void k1_conv(const float* __restrict__ fm) {
    extern __shared__ __align__(16) float smem1[];
    float* fms = smem1;                              // [g][c(128)][49]
    float* wts = smem1 + K1_FM_FLOATS;               // [c][16]
    ull* mbars = (ull*)(wts + 128 * KK);             // [2]

    const int q = blockIdx.x, bp = blockIdx.y;
    const int tid = threadIdx.x;
    const int lane = tid & 31, wid = tid >> 5;
    const int s = wid & 1, h = wid >> 1;
    const bool hi = (lane < 17);
    const int cbase = q * 128;

    uint32_t mb0 = smem_u32(&mbars[0]);
    uint32_t mb1 = smem_u32(&mbars[1]);
    if (tid == 0) { mbar_init1(mb0); mbar_init1(mb1); }
    __syncthreads();
    if (tid == 0) {
        mbar_expect(mb0, 4 * K1_CCH);
        mbar_expect(mb1, 4 * K1_CCH);
#pragma unroll
        for (int g = 0; g < 4; g++) {
            const float* src = fm + (size_t)(bp * 4 + g) * (CC * HWN)
                                  + (size_t)cbase * HWN;
            tma_bulk_1d(smem_u32(fms + g * 128 * HWN), src, K1_CCH, mb0);
        }
#pragma unroll
        for (int g = 0; g < 4; g++) {
            const float* src = fm + (size_t)(bp * 4 + g) * (CC * HWN)
                                  + (size_t)(cbase + 64) * HWN;
            tma_bulk_1d(smem_u32(fms + g * 128 * HWN + 64 * HWN), src, K1_CCH, mb1);
        }
    }
    // stage weights (8KB) while TMA flies
    {
        const float4* src = (const float4*)(g_wT + cbase * KK);
        for (int i = tid; i < (128 * KK) / 4; i += 128) ((float4*)wts)[i] = src[i];
    }
    __syncthreads();

    mbar_wait0(s == 0 ? mb0 : mb1);

    ull accA[4][4], accB[4][4];   // [g][k-pair within 8-k half]
#pragma unroll
    for (int g = 0; g < 4; g++)
#pragma unroll
        for (int p = 0; p < 4; p++) { accA[g][p] = 0ull; accB[g][p] = 0ull; }

    const int c0 = s * 64;
#pragma unroll 4
    for (int j = 0; j < 64; j++) {
        const int c = c0 + j;
        // weights: 8 k = 32B per lane, uniform (2x LDS.128)
        const ulonglong2* wp = (const ulonglong2*)(wts + c * KK + h * 8);
        ulonglong2 w01 = wp[0];   // k pairs (h8+0,h8+1),(h8+2,h8+3)
        // second 16B: careful — wts+c*16+h*8 + 4 floats
        ulonglong2 w23 = *(const ulonglong2*)(wts + c * KK + h * 8 + 4);

        ull wq0 = w01.x, wq1 = w01.y, wq2 = w23.x, wq3 = w23.y;

#pragma unroll
        for (int g = 0; g < 4; g++) {
            const float* row = fms + g * 128 * HWN + c * HWN;
            float v0 = row[lane];
            float v1 = hi ? row[lane + 32] : 0.0f;
            ull vv0 = pack2(v0, v0), vv1 = pack2(v1, v1);
            accA[g][0] = ffma2(wq0, vv0, accA[g][0]);
            accB[g][0] = ffma2(wq0, vv1, accB[g][0]);
            accA[g][1] = ffma2(wq1, vv0, accA[g][1]);
            accB[g][1] = ffma2(wq1, vv1, accB[g][1]);
            accA[g][2] = ffma2(wq2, vv0, accA[g][2]);
            accB[g][2] = ffma2(wq2, vv1, accB[g][2]);
            accA[g][3] = ffma2(wq3, vv0, accA[g][3]);
            accB[g][3] = ffma2(wq3, vv1, accB[g][3]);
        }
    }

    // store partials: slice = q*2 + s, k range = h*8..h*8+7
    const int slice = q * 2 + s;
#pragma unroll
    for (int g = 0; g < 4; g++) {
        float* dst = g_part + ((size_t)(bp * 4 + g) * 32 + slice) * 784;
#pragma unroll
        for (int p = 0; p < 4; p++) {
            const int k0 = h * 8 + 2 * p;
            float x, y;
            unpack2(accA[g][p], x, y);
            dst[k0 * 49 + lane] = x;
            dst[(k0 + 1) * 49 + lane] = y;
            if (hi) {
                float xx, yy;
                unpack2(accB[g][p], xx, yy);
                dst[k0 * 49 + lane + 32] = xx;
                dst[(k0 + 1) * 49 + lane + 32] = yy;
            }
        }
    }
}

// ============================================================================
// K1b: reduce 32 partials, apply BN, relayout [k*49+hw] -> [hw*16+k]
// ============================================================================
__global__ __launch_bounds__(784) void k1b_reduce() {
    const int b = blockIdx.x;
    const int o = threadIdx.x;
    const float* src = g_part + (size_t)b * 32 * 784;
    float s = 0.0f;
#pragma unroll
    for (int p = 0; p < 32; p++) s += src[p * 784 + o];
    int k = o / 49;
    int hw = o - k * 49;
    g_fc16[b * 784 + hw * 16 + k] = s * g_binv[k] + g_boff[k];
}

// ============================================================================
// K2: bilinear, staggered TMA. Block = (c-tile 512, b REVERSED), 128 thr,
// 4 c/thread. Warp w owns c-chunk w (128 c) and waits only mbar[w] (+mbar[0]
// which also carries fc16). fc quads via uniform LDS.128 depth-1 prefetch,
// amortized over 4 c = 32 FFMA2.
// ============================================================================
#define K2_CCH (128 * HWN * 4)             // 25088 per chunk
#define K2_FC_BYTES (784 * 4)
#define K2_SMEM (512 * HWN * 4 + K2_FC_BYTES + 64)

__global__ __launch_bounds__(128) void k2_bilinear(const float* __restrict__ fm,
                                                   float* __restrict__ out) {
    extern __shared__ __align__(16) float smem[];
    float* fms = smem;                       // [512][49]
    float* fcs = smem + 512 * HWN;           // [hw][16]
    ull* mbars = (ull*)(fcs + 784);          // [4]

    const int tid = threadIdx.x;
    const int lane = tid & 31, wid = tid >> 5;
    const int b = (BB - 1) - blockIdx.y;     // reverse-b: ride K1's L2 tail
    const int cbase = blockIdx.x * 512;

    uint32_t mb[4];
#pragma unroll
    for (int i = 0; i < 4; i++) mb[i] = smem_u32(&mbars[i]);
    if (tid == 0) {
#pragma unroll
        for (int i = 0; i < 4; i++) mbar_init1(mb[i]);
    }
    __syncthreads();
    if (tid == 0) {
        mbar_expect(mb[0], K2_CCH + K2_FC_BYTES);
        tma_bulk_1d(smem_u32(fms),
                    fm + (size_t)b * (CC * HWN) + (size_t)cbase * HWN,
                    K2_CCH, mb[0]);
        tma_bulk_1d(smem_u32(fcs), g_fc16 + (size_t)b * 784, K2_FC_BYTES, mb[0]);
#pragma unroll
        for (int w = 1; w < 4; w++) {
            mbar_expect(mb[w], K2_CCH);
            tma_bulk_1d(smem_u32(fms + w * 128 * HWN),
                        fm + (size_t)b * (CC * HWN)
                           + (size_t)(cbase + w * 128) * HWN,
                        K2_CCH, mb[w]);
        }
    }
    __syncthreads();   // mbar handles visible everywhere

    mbar_wait0(mb[0]);                 // fc16 (+chunk 0)
    if (wid != 0) mbar_wait0(mb[wid]); // own chunk

    // warp w: c_i = w*128 + i*32 + lane  (lane stride 49 floats: conflict-free)
    const float* r0 = &fms[(wid * 128 + lane) * HWN];
    const float* r1 = &fms[(wid * 128 + 32 + lane) * HWN];
    const float* r2 = &fms[(wid * 128 + 64 + lane) * HWN];
    const float* r3 = &fms[(wid * 128 + 96 + lane) * HWN];
    const ulonglong2* fq = (const ulonglong2*)fcs;

    ull acc[4][8];
#pragma unroll
    for (int i = 0; i < 4; i++)
#pragma unroll
        for (int j = 0; j < 8; j++) acc[i][j] = 0ull;

    ulonglong2 q0 = fq[0], q1 = fq[1], q2 = fq[2], q3 = fq[3];

#pragma unroll 7
    for (int hw = 0; hw < HWN; hw++) {
        ulonglong2 n0, n1, n2, n3;
        if (hw < HWN - 1) {
            n0 = fq[(hw + 1) * 4 + 0];
            n1 = fq[(hw + 1) * 4 + 1];
            n2 = fq[(hw + 1) * 4 + 2];
            n3 = fq[(hw + 1) * 4 + 3];
        }
        float va = r0[hw], vb = r1[hw], vc = r2[hw], vd = r3[hw];
        ull vva = pack2(va, va), vvb = pack2(vb, vb);
        ull vvc = pack2(vc, vc), vvd = pack2(vd, vd);

        acc[0][0] = ffma2(q0.x, vva, acc[0][0]);  acc[1][0] = ffma2(q0.x, vvb, acc[1][0]);
        acc[2][0] = ffma2(q0.x, vvc, acc[2][0]);  acc[3][0] = ffma2(q0.x, vvd, acc[3][0]);
        acc[0][1] = ffma2(q0.y, vva, acc[0][1]);  acc[1][1] = ffma2(q0.y, vvb, acc[1][1]);
        acc[2][1] = ffma2(q0.y, vvc, acc[2][1]);  acc[3][1] = ffma2(q0.y, vvd, acc[3][1]);
        acc[0][2] = ffma2(q1.x, vva, acc[0][2]);  acc[1][2] = ffma2(q1.x, vvb, acc[1][2]);
        acc[2][2] = ffma2(q1.x, vvc, acc[2][2]);  acc[3][2] = ffma2(q1.x, vvd, acc[3][2]);
        acc[0][3] = ffma2(q1.y, vva, acc[0][3]);  acc[1][3] = ffma2(q1.y, vvb, acc[1][3]);
        acc[2][3] = ffma2(q1.y, vvc, acc[2][3]);  acc[3][3] = ffma2(q1.y, vvd, acc[3][3]);
        acc[0][4] = ffma2(q2.x, vva, acc[0][4]);  acc[1][4] = ffma2(q2.x, vvb, acc[1][4]);
        acc[2][4] = ffma2(q2.x, vvc, acc[2][4]);  acc[3][4] = ffma2(q2.x, vvd, acc[3][4]);
        acc[0][5] = ffma2(q2.y, vva, acc[0][5]);  acc[1][5] = ffma2(q2.y, vvb, acc[1][5]);
        acc[2][5] = ffma2(q2.y, vvc, acc[2][5]);  acc[3][5] = ffma2(q2.y, vvd, acc[3][5]);
        acc[0][6] = ffma2(q3.x, vva, acc[0][6]);  acc[1][6] = ffma2(q3.x, vvb, acc[1][6]);
        acc[2][6] = ffma2(q3.x, vvc, acc[2][6]);  acc[3][6] = ffma2(q3.x, vvd, acc[3][6]);
        acc[0][7] = ffma2(q3.y, vva, acc[0][7]);  acc[1][7] = ffma2(q3.y, vvb, acc[1][7]);
        acc[2][7] = ffma2(q3.y, vvc, acc[2][7]);  acc[3][7] = ffma2(q3.y, vvd, acc[3][7]);

        q0 = n0; q1 = n1; q2 = n2; q3 = n3;
    }

#pragma unroll
    for (int i = 0; i < 4; i++) {
        float* ob = out + (size_t)b * 32768 + cbase + wid * 128 + i * 32 + lane;
#pragma unroll
        for (int kp = 0; kp < 8; kp++) {
            float x, y;
            unpack2(acc[i][kp], x, y);
            ob[(2 * kp) * 2048] = x;
            ob[(2 * kp + 1) * 2048] = y;
        }
    }
}

extern "C" void kernel_launch(void* const* d_in, const int* in_sizes, int n_in,
                              void* d_out, int out_size) {
    const float* fm  = (const float*)d_in[0];  // [256,2048,7,7]
    const float* w16 = (const float*)d_in[1];  // [16,2048]
    const float* bng = (const float*)d_in[2];
    const float* bnb = (const float*)d_in[3];
    const float* bnm = (const float*)d_in[4];
    const float* bnv = (const float*)d_in[5];
    float* out = (float*)d_out;

    cudaFuncSetAttribute(k1_conv, cudaFuncAttributeMaxDynamicSharedMemorySize,
                         K1_SMEM);
    cudaFuncSetAttribute(k2_bilinear, cudaFuncAttributeMaxDynamicSharedMemorySize,
                         K2_SMEM);

    k0_prep<<<(CC * KK + 255) / 256, 256>>>(w16, bng, bnb, bnm, bnv);
    dim3 g1(16, BB / 4);  // 1024 blocks: (q-slice of 128c, b-quad)
    k1_conv<<<g1, 128, K1_SMEM>>>(fm);
    k1b_reduce<<<BB, 784>>>();
    dim3 g2(4, BB);       // 1024 blocks: (c-tile of 512, b)
    k2_bilinear<<<g2, 128, K2_SMEM>>>(fm, out);
}